// round 13
// baseline (speedup 1.0000x reference)
#include <cuda_runtime.h>
#include <cuda_bf16.h>
#include <math.h>

// Problem dims
#define Vn 8000
#define Bn 64
#define Tn 256
#define Rn 1024
#define Un 512
#define Sn 1024
#define NROWS (Bn * Tn)  // 16384

#define NCTA 128
#define CH_COLS 256
#define ROW_STR 264                      // elems; 528 B rows

// smem W section offsets (elems). col stride = K+8 elems.
#define L0H 0
#define L0T 12352
#define L1H 24704
#define L1T 32960
#define L2H 41216
#define L2T 49472

// smem byte layout
#define OFF_BUF0 115456
#define BUF_B    33792                   // 64*264*2
#define OFF_HRAW (OFF_BUF0 + 3 * BUF_B)  // 216832
#define OFF_TRAW (OFF_HRAW + 2304)       // 219136
#define OFF_BARF (OFF_TRAW + 2304)       // 221440  full barriers x3
#define OFF_BARE (OFF_BARF + 24)         // 221464  empty barriers x3
#define SCAN_SMEM (OFF_BARE + 24)        // 221488

// ---------------- device scratch (static globals; no runtime allocation) ----
__device__ float g_states[Tn * Bn * Rn];   // [t][b][r] fp32 final states (for proj)
__device__ float g_outputs[NROWS * Un];
__device__ float g_slog[NROWS * Sn];
__device__ float g_tlog[NROWS];
__device__ float g_Ws[Sn * Un];
__device__ float g_svec[Sn];
__device__ int   g_sid[Sn];

// bf16 scan data
__device__ __nv_bfloat16 g_xb[NROWS * Un];                     // [t][b][u]
__device__ __nv_bfloat16 g_WbH[1024 * 1536 + 2 * 1024 * 1024]; // [j][k] x3 layers
__device__ __nv_bfloat16 g_WbT[1024 * 1536 + 2 * 1024 * 1024];
__device__ __nv_bfloat16 g_sB[2 * Bn * Rn];                    // ping-pong L2-out
__device__ __nv_bfloat16 g_tmpA_B[Bn * Rn];                    // L0 out
__device__ __nv_bfloat16 g_tmpB_B[Bn * Rn];                    // L1 out

// per-(phase,quarter) producer counters: monotonic within one launch
__device__ unsigned g_cnt[768 * 4];

// ---------------- helpers ---------------------------------------------------
__device__ __forceinline__ unsigned to_tf32(float x) {
    unsigned r;
    asm("cvt.rna.tf32.f32 %0, %1;" : "=r"(r) : "f"(x));
    return r;
}

__device__ __forceinline__ float tanhfast(float x) {
    float y;
    asm("tanh.approx.f32 %0, %1;" : "=f"(y) : "f"(x));
    return y;
}

__device__ __forceinline__ void mma8(float c[4],
                                     unsigned a0, unsigned a1, unsigned a2, unsigned a3,
                                     unsigned b0, unsigned b1) {
    asm volatile(
        "mma.sync.aligned.m16n8k8.row.col.f32.tf32.tf32.f32 "
        "{%0,%1,%2,%3},{%4,%5,%6,%7},{%8,%9},{%0,%1,%2,%3};"
        : "+f"(c[0]), "+f"(c[1]), "+f"(c[2]), "+f"(c[3])
        : "r"(a0), "r"(a1), "r"(a2), "r"(a3), "r"(b0), "r"(b1));
}

__device__ __forceinline__ void mma_bf16(float c[4],
                                         unsigned a0, unsigned a1, unsigned a2, unsigned a3,
                                         unsigned b0, unsigned b1) {
    asm volatile(
        "mma.sync.aligned.m16n8k16.row.col.f32.bf16.bf16.f32 "
        "{%0,%1,%2,%3},{%4,%5,%6,%7},{%8,%9},{%0,%1,%2,%3};"
        : "+f"(c[0]), "+f"(c[1]), "+f"(c[2]), "+f"(c[3])
        : "r"(a0), "r"(a1), "r"(a2), "r"(a3), "r"(b0), "r"(b1));
}

__device__ __forceinline__ void ldsm4(unsigned& a0, unsigned& a1,
                                      unsigned& a2, unsigned& a3, unsigned addr) {
    asm volatile("ldmatrix.sync.aligned.m8n8.x4.shared.b16 {%0,%1,%2,%3}, [%4];"
                 : "=r"(a0), "=r"(a1), "=r"(a2), "=r"(a3) : "r"(addr));
}

__device__ __forceinline__ void waitBar(unsigned barU, unsigned parity) {
    asm volatile(
        "{\n\t.reg .pred P;\n\t"
        "WB_%=:\n\t"
        "mbarrier.try_wait.parity.acquire.cta.shared::cta.b64 P, [%0], %1, 0x989680;\n\t"
        "@!P bra WB_%=;\n\t}"
        :: "r"(barU), "r"(parity) : "memory");
}

__device__ __forceinline__ void pollCnt(const unsigned* p) {
    unsigned v;
    for (;;) {
        asm volatile("ld.acquire.gpu.global.u32 %0, [%1];" : "=r"(v) : "l"(p));
        if (v >= 32u) break;
        __nanosleep(32);
    }
}

// ---------------- init ------------------------------------------------------
__global__ void __launch_bounds__(256) init_kernel(
    const int* __restrict__ sampled, const float* __restrict__ scnt,
    const float* __restrict__ sw, const float* __restrict__ sb,
    float* __restrict__ out)
{
    int gt = blockIdx.x * blockDim.x + threadIdx.x;
    int stride = gridDim.x * blockDim.x;
    if (gt == 0) out[0] = 0.0f;
    unsigned* sb32 = (unsigned*)g_sB;   // both ping-pong slots as words
    for (int i = gt; i < Bn * Rn; i += stride) sb32[i] = 0u;
    for (int i = gt; i < 768 * 4; i += stride) g_cnt[i] = 0u;
    for (int j = gt; j < Sn; j += stride) {
        int id = sampled[j];
        g_sid[j] = id;
        g_svec[j] = sb[id] - logf(scnt[j]);
    }
    for (int i = gt; i < Sn * Un; i += stride)
        g_Ws[i] = sw[(size_t)sampled[i >> 9] * Un + (i & 511)];
}

// ---------------- weight transpose/convert: f32 [K][1024] -> bf16 [1024][K] -
__global__ void __launch_bounds__(256) wconv_kernel(
    const float* __restrict__ src, int which, size_t dstOff, int K)
{
    __shared__ float tile[32][33];
    __nv_bfloat16* dst = (which ? g_WbT : g_WbH) + dstOff;
    int k0 = blockIdx.x * 32, j0 = blockIdx.y * 32;
    int tx = threadIdx.x & 31, ty = threadIdx.x >> 5;
    for (int r = ty; r < 32; r += 8)
        tile[r][tx] = src[(size_t)(k0 + r) * 1024 + j0 + tx];
    __syncthreads();
    for (int r = ty; r < 32; r += 8)
        dst[(size_t)(j0 + r) * K + k0 + tx] = __float2bfloat16_rn(tile[tx][r]);
}

// ---------------- emb pre-gather --------------------------------------------
__global__ void __launch_bounds__(128) xconv_kernel(
    const int* __restrict__ inp, const float* __restrict__ emb)
{
    int idx = blockIdx.x;               // t*64 + b
    int b = idx & 63, t = idx >> 6;
    int tok = inp[b * Tn + t];
    const float4* s = (const float4*)(emb + (size_t)tok * Un);
    __nv_bfloat162* d2 = (__nv_bfloat162*)(g_xb + (size_t)idx * Un);
    int v = threadIdx.x;
    float4 f = s[v];
    __nv_bfloat162 p0, p1;
    p0.x = __float2bfloat16_rn(f.x); p0.y = __float2bfloat16_rn(f.y);
    p1.x = __float2bfloat16_rn(f.z); p1.y = __float2bfloat16_rn(f.w);
    d2[2 * v] = p0;
    d2[2 * v + 1] = p1;
}

// ---------------- producer: issue one phase's chunks ------------------------
template<int NCH, int nEmb>
__device__ __forceinline__ void producerPhase(
    int rot, int waitPhase,
    const __nv_bfloat16* __restrict__ aEmb,
    const __nv_bfloat16* __restrict__ aState,
    unsigned smemU, int lane, int& slot, unsigned& eP)
{
    #pragma unroll
    for (int c = 0; c < NCH; c++) {
        int lc = (c < nEmb) ? c : nEmb + ((rot + (c - nEmb)) & 3);
        const __nv_bfloat16* src; int stride; int wi = -1;
        if (lc < nEmb) { src = aEmb + lc * CH_COLS; stride = Un; }
        else {
            int gi = lc - nEmb;
            src = aState + (gi << 8); stride = Rn;
            if (waitPhase >= 0) wi = waitPhase * 4 + gi;
        }
        unsigned ebar = smemU + OFF_BARE + slot * 8;
        unsigned fbar = smemU + OFF_BARF + slot * 8;
        waitBar(ebar, (eP >> slot) & 1u);
        eP ^= (1u << slot);
        if (lane == 0 && wi >= 0) pollCnt(&g_cnt[wi]);
        __syncwarp();
        if (lane == 0)
            asm volatile("mbarrier.arrive.expect_tx.shared.b64 _, [%0], %1;"
                         :: "r"(fbar), "r"(32768) : "memory");
        __syncwarp();
        unsigned bufU = smemU + OFF_BUF0 + slot * BUF_B;
        #pragma unroll
        for (int r = 0; r < 2; r++) {
            int row = lane + r * 32;
            asm volatile(
                "cp.async.bulk.shared::cluster.global.mbarrier::complete_tx::bytes "
                "[%0], [%1], %2, [%3];"
                :: "r"(bufU + (unsigned)row * (ROW_STR * 2)),
                   "l"(src + (size_t)row * stride), "r"(512), "r"(fbar)
                : "memory");
        }
        slot = (slot == 2) ? 0 : slot + 1;
    }
}

// ---------------- consumer: one highway phase (dual GEMM + gate) ------------
template<int K, int NCH, int nEmb>
__device__ __forceinline__ void computePhase(
    int rot, int pIdx, int offHElems, int offTElems,
    float biasH, float biasT, float& s0, float& s1,
    __nv_bfloat16* __restrict__ dstB,
    float* __restrict__ stF,           // nullable (layer 2 only)
    char* smem, unsigned smemU,
    int& slot, unsigned& fP,
    int jbase, int tid, int w, int lane)
{
    const int g = lane >> 2, tig = lane & 3;
    const int mat = w >> 2, rbase = (w & 3) * 16;
    const int strW = K + 8;

    const unsigned lmOff = (unsigned)(((rbase + (lane & 15)) * ROW_STR
                                       + ((lane >> 4) << 3)) * 2);

    float acc0[4] = {0.f, 0.f, 0.f, 0.f}, acc1[4] = {0.f, 0.f, 0.f, 0.f};
    const unsigned* bw = (const unsigned*)((const __nv_bfloat16*)smem
                          + (mat ? offTElems : offHElems) + g * strW);

    #pragma unroll
    for (int c = 0; c < NCH; c++) {
        int lc = (c < nEmb) ? c : nEmb + ((rot + (c - nEmb)) & 3);
        unsigned fbar = smemU + OFF_BARF + slot * 8;
        waitBar(fbar, (fP >> slot) & 1u);
        fP ^= (1u << slot);

        unsigned aAddr = smemU + OFF_BUF0 + slot * BUF_B + lmOff;
        const unsigned* br = bw + (lc << 7) + tig;
        #pragma unroll
        for (int s8 = 0; s8 < 16; s8++) {
            unsigned a0, a1, a2, a3;
            ldsm4(a0, a1, a2, a3, aAddr + s8 * 32);
            unsigned b0 = br[s8 * 8], b1 = br[s8 * 8 + 4];
            if (s8 & 1) mma_bf16(acc1, a0, a1, a2, a3, b0, b1);
            else        mma_bf16(acc0, a0, a1, a2, a3, b0, b1);
        }
        __syncwarp();
        if (lane == 0)
            asm volatile("mbarrier.arrive.shared.b64 _, [%0];"
                         :: "r"(smemU + OFF_BARE + slot * 8) : "memory");
        slot = (slot == 2) ? 0 : slot + 1;
    }

    float* hraw = (float*)(smem + OFF_HRAW);
    float* traw = (float*)(smem + OFF_TRAW);
    float* raw = mat ? traw : hraw;
    int r0 = rbase + g;
    raw[r0 * 9 + 2 * tig]           = acc0[0] + acc1[0];
    raw[r0 * 9 + 2 * tig + 1]       = acc0[1] + acc1[1];
    raw[(r0 + 8) * 9 + 2 * tig]     = acc0[2] + acc1[2];
    raw[(r0 + 8) * 9 + 2 * tig + 1] = acc0[3] + acc1[3];
    asm volatile("bar.sync 2, 256;" ::: "memory");

    // epilogue: thread owns rows (tid>>3) and (tid>>3)+32 at col jbase+(tid&7)
    int jj = tid & 7, jcol = jbase + jj, b0r = tid >> 3;
    {
        float hp = hraw[b0r * 9 + jj] + biasH;
        float tp = traw[b0r * 9 + jj] + biasT;
        float tg = 1.0f / (1.0f + __expf(-tp));
        float o = (tanhfast(hp) - s0) * tg + s0;
        s0 = o;
        dstB[b0r * Rn + jcol] = __float2bfloat16_rn(o);
        if (stF) stF[b0r * Rn + jcol] = o;
    }
    {
        int b1r = b0r + 32;
        float hp = hraw[b1r * 9 + jj] + biasH;
        float tp = traw[b1r * 9 + jj] + biasT;
        float tg = 1.0f / (1.0f + __expf(-tp));
        float o = (tanhfast(hp) - s1) * tg + s1;
        s1 = o;
        dstB[b1r * Rn + jcol] = __float2bfloat16_rn(o);
        if (stF) stF[b1r * Rn + jcol] = o;
    }
    asm volatile("bar.sync 2, 256;" ::: "memory");
    if (tid == 0)
        asm volatile("red.release.gpu.global.add.u32 [%0], %1;"
                     :: "l"(&g_cnt[pIdx * 4 + (blockIdx.x >> 5)]), "r"(1u) : "memory");
}

// ---------------- persistent scan kernel (8 compute warps + 1 producer) -----
__global__ void __launch_bounds__(288) scan_kernel(
    const float* __restrict__ bh0, const float* __restrict__ bt0,
    const float* __restrict__ bh, const float* __restrict__ bt)
{
    extern __shared__ char smem[];
    const unsigned smemU = (unsigned)__cvta_generic_to_shared(smem);
    const int tid = threadIdx.x, w = tid >> 5, lane = tid & 31;
    const int jbase = blockIdx.x * 8;
    const int rot = ((blockIdx.x >> 5) + 1) & 3;
    const size_t GOFF1 = (size_t)1024 * 1536;
    const size_t GOFF2 = GOFF1 + (size_t)1024 * 1024;

    // preload this CTA's weight slice into smem (once; all 288 threads)
    {
        const int Ks[6] = {1536, 1536, 1024, 1024, 1024, 1024};
        const int so[6] = {L0H, L0T, L1H, L1T, L2H, L2T};
        const size_t go[6] = {0, 0, GOFF1, GOFF1, GOFF2, GOFF2};
        __nv_bfloat16* wsm = (__nv_bfloat16*)smem;
        for (int sec = 0; sec < 6; sec++) {
            const __nv_bfloat16* gsrc = ((sec & 1) ? g_WbT : g_WbH)
                                        + go[sec] + (size_t)jbase * Ks[sec];
            int kv = Ks[sec] >> 3;            // uint4 per col
            int nv = Ks[sec];                 // 8 cols * kv
            for (int i = tid; i < nv; i += 288) {
                int col = i / kv, vi = i - col * kv;
                *(uint4*)(wsm + so[sec] + col * (Ks[sec] + 8) + vi * 8) =
                    *(const uint4*)(gsrc + (size_t)col * Ks[sec] + vi * 8);
            }
        }
    }
    if (tid == 0) {
        #pragma unroll
        for (int s = 0; s < 3; s++) {
            asm volatile("mbarrier.init.shared.b64 [%0], 1;"
                         :: "r"(smemU + OFF_BARF + s * 8) : "memory");
            asm volatile("mbarrier.init.shared.b64 [%0], 8;"
                         :: "r"(smemU + OFF_BARE + s * 8) : "memory");
        }
    }
    __syncthreads();

    if (tid >= 256) {
        // ---- producer warp ----
        int slot = 0;
        unsigned eP = 0x7u;                // empty-wait parities start at 1
        for (int t = 0; t < Tn; t++) {
            const __nv_bfloat16* xbt = g_xb + (size_t)t * Bn * Un;
            const __nv_bfloat16* prevL2 = g_sB + (size_t)((t + 1) & 1) * Bn * Rn;
            int p = 3 * t;
            producerPhase<6, 2>(rot, (t ? p - 1 : -1), xbt, prevL2,
                                smemU, lane, slot, eP);
            producerPhase<4, 0>(rot, p, nullptr, g_tmpA_B, smemU, lane, slot, eP);
            producerPhase<4, 0>(rot, p + 1, nullptr, g_tmpB_B, smemU, lane, slot, eP);
        }
    } else {
        // ---- compute warps ----
        int jcol = jbase + (tid & 7);
        float b0H = __ldg(&bh0[jcol]), b0T = __ldg(&bt0[jcol]);
        float b1H = __ldg(&bh[jcol]),  b1T = __ldg(&bt[jcol]);
        float b2H = __ldg(&bh[Rn + jcol]), b2T = __ldg(&bt[Rn + jcol]);

        float s0 = 0.f, s1 = 0.f;
        int slot = 0;
        unsigned fP = 0u;

        for (int t = 0; t < Tn; t++) {
            int p = 3 * t;
            computePhase<1536, 6, 2>(rot, p, L0H, L0T, b0H, b0T, s0, s1,
                                     g_tmpA_B, nullptr, smem, smemU,
                                     slot, fP, jbase, tid, w, lane);
            computePhase<1024, 4, 0>(rot, p + 1, L1H, L1T, b1H, b1T, s0, s1,
                                     g_tmpB_B, nullptr, smem, smemU,
                                     slot, fP, jbase, tid, w, lane);
            computePhase<1024, 4, 0>(rot, p + 2, L2H, L2T, b2H, b2T, s0, s1,
                                     g_sB + (size_t)(t & 1) * Bn * Rn,
                                     g_states + (size_t)t * Bn * Rn,
                                     smem, smemU, slot, fP, jbase, tid, w, lane);
        }
    }
}

// ---------------- projection: outputs[m][u] = states . Wp + bp --------------
__global__ void __launch_bounds__(256) proj_kernel(
    const float* __restrict__ Wp, const float* __restrict__ bp)
{
    __shared__ float AS[64][33];
    __shared__ float BS[32][65];

    const int tid = threadIdx.x;
    const int warp = tid >> 5, lane = tid & 31;
    const int g = lane >> 2, tig = lane & 3;
    const int rbase = (warp >> 1) * 16;
    const int cbase = (warp & 1) * 32;
    const int m0 = blockIdx.x * 64, jb = blockIdx.y * 64;

    float c[4][4];
    #pragma unroll
    for (int nt = 0; nt < 4; nt++)
        #pragma unroll
        for (int i = 0; i < 4; i++) c[nt][i] = 0.f;

    for (int t0 = 0; t0 < Rn; t0 += 32) {
        #pragma unroll
        for (int r = 0; r < 2; r++) {
            int v = r * 256 + tid;
            int row = v >> 3, q = v & 7;
            int m = m0 + row;
            const float* p = g_states + (size_t)(m & (Tn - 1)) * (Bn * Rn)
                                      + (size_t)(m >> 8) * Rn + t0 + q * 4;
            float4 f = *(const float4*)p;
            AS[row][q*4+0] = __uint_as_float(to_tf32(f.x));
            AS[row][q*4+1] = __uint_as_float(to_tf32(f.y));
            AS[row][q*4+2] = __uint_as_float(to_tf32(f.z));
            AS[row][q*4+3] = __uint_as_float(to_tf32(f.w));
        }
        #pragma unroll
        for (int r = 0; r < 2; r++) {
            int v = r * 256 + tid;
            int kk = v >> 4, jq = v & 15;
            float4 f = *(const float4*)(Wp + (size_t)(t0 + kk) * Un + jb + jq * 4);
            BS[kk][jq*4+0] = __uint_as_float(to_tf32(f.x));
            BS[kk][jq*4+1] = __uint_as_float(to_tf32(f.y));
            BS[kk][jq*4+2] = __uint_as_float(to_tf32(f.z));
            BS[kk][jq*4+3] = __uint_as_float(to_tf32(f.w));
        }
        __syncthreads();

        #pragma unroll
        for (int k8 = 0; k8 < 32; k8 += 8) {
            unsigned a0 = __float_as_uint(AS[rbase + g    ][k8 + tig    ]);
            unsigned a1 = __float_as_uint(AS[rbase + g + 8][k8 + tig    ]);
            unsigned a2 = __float_as_uint(AS[rbase + g    ][k8 + tig + 4]);
            unsigned a3 = __float_as_uint(AS[rbase + g + 8][k8 + tig + 4]);
            #pragma unroll
            for (int nt = 0; nt < 4; nt++) {
                int j = cbase + nt * 8 + g;
                unsigned b0 = __float_as_uint(BS[k8 + tig    ][j]);
                unsigned b1 = __float_as_uint(BS[k8 + tig + 4][j]);
                mma8(c[nt], a0, a1, a2, a3, b0, b1);
            }
        }
        __syncthreads();
    }

    #pragma unroll
    for (int nt = 0; nt < 4; nt++) {
        #pragma unroll
        for (int i = 0; i < 4; i++) {
            int m = m0 + rbase + g + ((i >= 2) ? 8 : 0);
            int j = jb + cbase + nt * 8 + tig * 2 + (i & 1);
            g_outputs[(size_t)m * Un + j] = c[nt][i] + bp[j];
        }
    }
}

// ---------------- sampled logits: outputs @ Ws^T + svec, hit mask -----------
__global__ void __launch_bounds__(256) slog_kernel(const int* __restrict__ labels)
{
    __shared__ float AS[64][33];
    __shared__ float BS[32][65];

    const int tid = threadIdx.x;
    const int warp = tid >> 5, lane = tid & 31;
    const int g = lane >> 2, tig = lane & 3;
    const int rbase = (warp >> 1) * 16;
    const int cbase = (warp & 1) * 32;
    const int m0 = blockIdx.x * 64, jb = blockIdx.y * 64;

    float c[4][4];
    #pragma unroll
    for (int nt = 0; nt < 4; nt++)
        #pragma unroll
        for (int i = 0; i < 4; i++) c[nt][i] = 0.f;

    for (int t0 = 0; t0 < Un; t0 += 32) {
        #pragma unroll
        for (int r = 0; r < 2; r++) {
            int v = r * 256 + tid;
            int row = v >> 3, q = v & 7;
            const float* p = g_outputs + (size_t)(m0 + row) * Un + t0 + q * 4;
            float4 f = *(const float4*)p;
            AS[row][q*4+0] = __uint_as_float(to_tf32(f.x));
            AS[row][q*4+1] = __uint_as_float(to_tf32(f.y));
            AS[row][q*4+2] = __uint_as_float(to_tf32(f.z));
            AS[row][q*4+3] = __uint_as_float(to_tf32(f.w));
        }
        #pragma unroll
        for (int r = 0; r < 2; r++) {
            int v = r * 256 + tid;
            int j = v >> 3, q = v & 7;
            float4 f = *(const float4*)(g_Ws + (size_t)(jb + j) * Un + t0 + q * 4);
            BS[q*4+0][j] = __uint_as_float(to_tf32(f.x));
            BS[q*4+1][j] = __uint_as_float(to_tf32(f.y));
            BS[q*4+2][j] = __uint_as_float(to_tf32(f.z));
            BS[q*4+3][j] = __uint_as_float(to_tf32(f.w));
        }
        __syncthreads();

        #pragma unroll
        for (int k8 = 0; k8 < 32; k8 += 8) {
            unsigned a0 = __float_as_uint(AS[rbase + g    ][k8 + tig    ]);
            unsigned a1 = __float_as_uint(AS[rbase + g + 8][k8 + tig    ]);
            unsigned a2 = __float_as_uint(AS[rbase + g    ][k8 + tig + 4]);
            unsigned a3 = __float_as_uint(AS[rbase + g + 8][k8 + tig + 4]);
            #pragma unroll
            for (int nt = 0; nt < 4; nt++) {
                int j = cbase + nt * 8 + g;
                unsigned b0 = __float_as_uint(BS[k8 + tig    ][j]);
                unsigned b1 = __float_as_uint(BS[k8 + tig + 4][j]);
                mma8(c[nt], a0, a1, a2, a3, b0, b1);
            }
        }
        __syncthreads();
    }

    #pragma unroll
    for (int nt = 0; nt < 4; nt++) {
        #pragma unroll
        for (int i = 0; i < 4; i++) {
            int m = m0 + rbase + g + ((i >= 2) ? 8 : 0);
            int j = jb + cbase + nt * 8 + tig * 2 + (i & 1);
            float v = c[nt][i] + g_svec[j];
            if (labels[m] == g_sid[j]) v -= 1e9f;
            g_slog[(size_t)m * Sn + j] = v;
        }
    }
}

// ---------------- true logits: warp per row ---------------------------------
__global__ void __launch_bounds__(256) tlog_kernel(
    const int* __restrict__ labels, const float* __restrict__ sw,
    const float* __restrict__ sb, const float* __restrict__ tcnt)
{
    int warp = threadIdx.x >> 5, lane = threadIdx.x & 31;
    int n = blockIdx.x * 8 + warp;
    int lab = labels[n];
    const float4* o = (const float4*)(g_outputs + (size_t)n * Un);
    const float4* w = (const float4*)(sw + (size_t)lab * Un);
    float acc = 0.f;
    #pragma unroll
    for (int q = 0; q < 4; q++) {
        float4 a = o[lane + q * 32];
        float4 b = w[lane + q * 32];
        acc += a.x * b.x + a.y * b.y + a.z * b.z + a.w * b.w;
    }
    #pragma unroll
    for (int s = 16; s; s >>= 1) acc += __shfl_xor_sync(0xffffffffu, acc, s);
    if (lane == 0) g_tlog[n] = acc + sb[lab] - logf(tcnt[n]);
}

// ---------------- loss: warp per row, online logsumexp ----------------------
__global__ void __launch_bounds__(256) loss_kernel(float* __restrict__ out)
{
    __shared__ float red[8];
    int warp = threadIdx.x >> 5, lane = threadIdx.x & 31;
    int n = blockIdx.x * 8 + warp;

    float mL = -INFINITY, sL = 0.f;
    const float* row = g_slog + (size_t)n * Sn;
    for (int j = lane; j < Sn; j += 32) {
        float v = row[j];
        if (v > mL) { sL = sL * __expf(mL - v) + 1.f; mL = v; }
        else          sL += __expf(v - mL);
    }
    #pragma unroll
    for (int s = 16; s; s >>= 1) {
        float m2 = __shfl_xor_sync(0xffffffffu, mL, s);
        float s2 = __shfl_xor_sync(0xffffffffu, sL, s);
        float M = fmaxf(mL, m2);
        sL = sL * __expf(mL - M) + s2 * __expf(m2 - M);
        mL = M;
    }
    float z0 = g_tlog[n];
    float M = fmaxf(mL, z0);
    float S = sL * __expf(mL - M) + __expf(z0 - M);
    float loss = (M + logf(S)) - z0;

    if (lane == 0) red[warp] = loss;
    __syncthreads();
    if (threadIdx.x == 0) {
        float t = 0.f;
        #pragma unroll
        for (int i = 0; i < 8; i++) t += red[i];
        atomicAdd(out, t * (1.0f / NROWS));
    }
}

// ---------------- launch ----------------------------------------------------
extern "C" void kernel_launch(void* const* d_in, const int* in_sizes, int n_in,
                              void* d_out, int out_size)
{
    (void)in_sizes; (void)n_in; (void)out_size;

    const int*   input   = (const int*)  d_in[0];
    const int*   targets = (const int*)  d_in[1];
    const int*   sampled = (const int*)  d_in[2];
    const float* tcnt    = (const float*)d_in[3];
    const float* scnt    = (const float*)d_in[4];
    const float* emb     = (const float*)d_in[5];
    const float* Wh0     = (const float*)d_in[6];
    const float* bh0     = (const float*)d_in[7];
    const float* Wt0     = (const float*)d_in[8];
    const float* bt0     = (const float*)d_in[9];
    const float* Wh      = (const float*)d_in[10];
    const float* bh      = (const float*)d_in[11];
    const float* Wt      = (const float*)d_in[12];
    const float* bt      = (const float*)d_in[13];
    const float* Wp      = (const float*)d_in[14];
    const float* bp      = (const float*)d_in[15];
    const float* sw      = (const float*)d_in[16];
    const float* sb      = (const float*)d_in[17];
    float* out = (float*)d_out;

    const size_t OFF1 = (size_t)1024 * 1536;
    const size_t OFF2 = OFF1 + (size_t)1024 * 1024;

    cudaFuncSetAttribute(scan_kernel,
                         cudaFuncAttributeMaxDynamicSharedMemorySize, SCAN_SMEM);

    init_kernel<<<256, 256>>>(sampled, scnt, sw, sb, out);

    wconv_kernel<<<dim3(48, 32), 256>>>(Wh0, 0, 0, 1536);
    wconv_kernel<<<dim3(48, 32), 256>>>(Wt0, 1, 0, 1536);
    wconv_kernel<<<dim3(32, 32), 256>>>(Wh,                   0, OFF1, 1024);
    wconv_kernel<<<dim3(32, 32), 256>>>(Wt,                   1, OFF1, 1024);
    wconv_kernel<<<dim3(32, 32), 256>>>(Wh + (size_t)Rn * Rn, 0, OFF2, 1024);
    wconv_kernel<<<dim3(32, 32), 256>>>(Wt + (size_t)Rn * Rn, 1, OFF2, 1024);

    xconv_kernel<<<NROWS, 128>>>(input, emb);

    scan_kernel<<<NCTA, 288, SCAN_SMEM>>>(bh0, bt0, bh, bt);

    proj_kernel<<<dim3(NROWS / 64, Un / 64), 256>>>(Wp, bp);
    slog_kernel<<<dim3(NROWS / 64, Sn / 64), 256>>>(targets);
    tlog_kernel<<<NROWS / 8, 256>>>(targets, sw, sb, tcnt);
    loss_kernel<<<NROWS / 8, 256>>>(out);
}